// round 13
// baseline (speedup 1.0000x reference)
#include <cuda_runtime.h>
#include <cuda_bf16.h>
#include <cuda_fp16.h>
#include <math.h>
#include <stdint.h>

#define NN    50000
#define FEAT  128
#define HID   256
#define K0    160        // layer-0 K (129 live -> 132 used) padded to 160
#define NE    800000
#define NSUB  512
#define SUBSZ 64
#define MTOT  (NSUB*SUBSZ)

#define SCAN_B 256
#define NBLK   ((NN + SCAN_B - 1) / SCAN_B)   // 196

#define RB1   196                 // 128-row blocks in half 1
#define ROWS1 (RB1*128)           // 25088
#define RB2   195                 // remaining blocks (rows 25088..49999)

// ---------------- scratch (device globals; no allocation allowed) ----------------
__device__ __align__(16) __half         g_MSG[NN*HID];   // fp16 GEMM A (160-col view for L0)
__device__ __align__(16) __nv_bfloat16  g_B0 [NN*K0];    // bf16 h0
__device__ __align__(16) __nv_bfloat16  g_BA [NN*HID];   // bf16 h (layers)
__device__ __align__(16) __nv_bfloat16  g_BB [NN*HID];
__device__ __align__(16) __half         g_W0h[K0*HID];   // fp16 zero-padded W0
__device__ __align__(16) __half         g_W1h[HID*HID];
__device__ __align__(16) __half         g_W2h[HID*HID];
__device__ __align__(16) float          g_Z  [NSUB*4*HID];
// CSR scratch
__device__ int   g_deg [NN];
__device__ int   g_cur [NN];
__device__ int   g_off [NN+1];
__device__ int   g_bsum[NBLK];
__device__ __align__(8) int2 g_cpak[NE];    // packed (src, w_bits)

__device__ __forceinline__ __nv_bfloat16* gbuf16(int id){
    switch(id){
        case 0: return g_B0;
        case 1: return g_BA;
        default: return g_BB;
    }
}

// ---------------- setup ----------------
__global__ void build_h0(const float* __restrict__ x){
    int idx = blockIdx.x*blockDim.x + threadIdx.x;
    const int total = NN*K0;
    for (; idx < total; idx += gridDim.x*blockDim.x){
        int i = idx / K0;
        int c = idx - i*K0;
        g_B0[idx] = (c < FEAT) ? __float2bfloat16(x[i*FEAT + c]) : __float2bfloat16(0.f);
    }
}

__global__ void scatter_batch(const int* __restrict__ batches){
    int m = blockIdx.x*blockDim.x + threadIdx.x;
    if (m < MTOT) g_B0[(size_t)batches[m]*K0 + FEAT] = __float2bfloat16(1.0f);
}

__global__ void build_w0h(const float* __restrict__ W0){
    int idx = blockIdx.x*blockDim.x + threadIdx.x;
    if (idx < K0*HID){
        int r = idx / HID;
        int c = idx - r*HID;
        g_W0h[idx] = (r < FEAT+1) ? __float2half(W0[r*HID + c]) : __float2half(0.f);
    }
}

__global__ void build_wh(const float* __restrict__ W, int sel){
    __half* dst = (sel == 1) ? g_W1h : g_W2h;
    int i = blockIdx.x*blockDim.x + threadIdx.x;
    if (i < HID*HID) dst[i] = __float2half(W[i]);
}

// ---------------- CSR build ----------------
__global__ void zero_degcur(){
    int i = blockIdx.x*blockDim.x + threadIdx.x;
    if (i < NN){ g_deg[i] = 0; g_cur[i] = 0; }
}

__global__ void hist_dst(const int* __restrict__ dst){
    int e = blockIdx.x*blockDim.x + threadIdx.x;
    if (e < NE) atomicAdd(&g_deg[dst[e]], 1);
}

__global__ void scan_block(){
    __shared__ int sh[SCAN_B];
    int i = blockIdx.x*SCAN_B + threadIdx.x;
    int v = (i < NN) ? g_deg[i] : 0;
    sh[threadIdx.x] = v;
    __syncthreads();
    #pragma unroll
    for (int off = 1; off < SCAN_B; off <<= 1){
        int add = (threadIdx.x >= off) ? sh[threadIdx.x - off] : 0;
        __syncthreads();
        sh[threadIdx.x] += add;
        __syncthreads();
    }
    if (i < NN) g_off[i] = sh[threadIdx.x] - v;
    if (threadIdx.x == SCAN_B-1) g_bsum[blockIdx.x] = sh[SCAN_B-1];
}

__global__ void scan_bsums(){
    __shared__ int sh[256];
    int t = threadIdx.x;
    int v = (t < NBLK) ? g_bsum[t] : 0;
    sh[t] = v;
    __syncthreads();
    #pragma unroll
    for (int off = 1; off < 256; off <<= 1){
        int add = (t >= off) ? sh[t - off] : 0;
        __syncthreads();
        sh[t] += add;
        __syncthreads();
    }
    if (t < NBLK) g_bsum[t] = sh[t] - v;
}

__global__ void scan_add(){
    int i = blockIdx.x*SCAN_B + threadIdx.x;
    if (i < NN) g_off[i] += g_bsum[blockIdx.x];
    if (i == 0) g_off[NN] = NE;
}

__global__ void csr_scatter(const int* __restrict__ src, const int* __restrict__ dst,
                            const float* __restrict__ ew){
    int e = blockIdx.x*blockDim.x + threadIdx.x;
    if (e < NE){
        int d = dst[e];
        int pos = g_off[d] + atomicAdd(&g_cur[d], 1);
        g_cpak[pos] = make_int2(src[e], __float_as_int(ew[e]));
    }
}

// ---------------- gather (bf16 inputs, f32 accumulate, fp16 output) ----------------
__device__ __forceinline__ void facc(float4& a, float w, uint2 u){
    float2 f0 = __bfloat1622float2(*(__nv_bfloat162*)&u.x);
    float2 f1 = __bfloat1622float2(*(__nv_bfloat162*)&u.y);
    a.x += w*f0.x; a.y += w*f0.y; a.z += w*f1.x; a.w += w*f1.y;
}
__device__ __forceinline__ uint2 f4toh4(float4 a){
    __half2 lo = __floats2half2_rn(a.x, a.y);
    __half2 hi = __floats2half2_rn(a.z, a.w);
    return make_uint2(*(uint32_t*)&lo, *(uint32_t*)&hi);
}

__global__ __launch_bounds__(256)
void csr_gather(int hsel, const float* __restrict__ eps, int ei, int ld,
                int w4r, int w4p, int n0, int n1){
    const __nv_bfloat16* h = gbuf16(hsel);
    int n = n0 + blockIdx.x*8 + (threadIdx.x >> 5);
    if (n >= n1) return;
    int lane = threadIdx.x & 31;
    int s0 = g_off[n], s1 = g_off[n+1];

    const bool a0 = (lane      < w4r);
    const bool a1 = (lane + 32 < w4r);
    float4 acc0 = make_float4(0.f,0.f,0.f,0.f);
    float4 acc1 = make_float4(0.f,0.f,0.f,0.f);

    int e = s0;
    for (; e + 4 <= s1; e += 4){
        int2 p[4];
        #pragma unroll
        for (int j=0;j<4;j++)
            p[j] = __ldg(&g_cpak[e+j]);
        uint2 u0[4], u1[4];
        #pragma unroll
        for (int j=0;j<4;j++){
            const uint2* hs = (const uint2*)(h + (size_t)p[j].x*ld);
            if (a0) u0[j] = __ldg(&hs[lane]);
            if (a1) u1[j] = __ldg(&hs[lane+32]);
        }
        #pragma unroll
        for (int j=0;j<4;j++){
            float w = __int_as_float(p[j].y);
            if (a0) facc(acc0, w, u0[j]);
            if (a1) facc(acc1, w, u1[j]);
        }
    }
    for (; e < s1; e++){
        int2 p = __ldg(&g_cpak[e]);
        float w = __int_as_float(p.y);
        const uint2* hs = (const uint2*)(h + (size_t)p.x*ld);
        if (a0){ uint2 u = __ldg(&hs[lane]);    facc(acc0, w, u); }
        if (a1){ uint2 u = __ldg(&hs[lane+32]); facc(acc1, w, u); }
    }

    const float ep = 1.0f + eps[ei];
    const uint2* hn = (const uint2*)(h + (size_t)n*ld);
    uint2* mrow = (uint2*)(g_MSG + (size_t)n*ld);
    if (a0){
        uint2 u = __ldg(&hn[lane]);
        facc(acc0, ep, u);
        mrow[lane] = f4toh4(acc0);
    }
    if (a1){
        uint2 u = __ldg(&hn[lane+32]);
        facc(acc1, ep, u);
        mrow[lane+32] = f4toh4(acc1);
    } else if (lane + 32 < w4p){
        mrow[lane+32] = make_uint2(0u, 0u);
    }
}

// ---------------- tensor-core GIN GEMM: outb16 = relu(MSG @ W + b) ------
// pure fp16, BK=32, cp.async double-buffered, 1 sync per kstep.
__device__ __forceinline__ uint32_t sptr(const void* p){
    return (uint32_t)__cvta_generic_to_shared(p);
}
__device__ __forceinline__ void cpa16(uint32_t smem, const void* g, int nbytes){
    asm volatile("cp.async.cg.shared.global [%0], [%1], 16, %2;"
                 :: "r"(smem), "l"(g), "r"(nbytes) : "memory");
}
#define CP_COMMIT() asm volatile("cp.async.commit_group;" ::: "memory")
#define CP_WAIT0()  asm volatile("cp.async.wait_group 0;" ::: "memory")

__device__ __forceinline__ void ldsm4(uint32_t& r0,uint32_t& r1,uint32_t& r2,uint32_t& r3, uint32_t a){
    asm volatile("ldmatrix.sync.aligned.m8n8.x4.shared.b16 {%0,%1,%2,%3},[%4];"
                 : "=r"(r0),"=r"(r1),"=r"(r2),"=r"(r3) : "r"(a));
}
__device__ __forceinline__ void ldsm4t(uint32_t& r0,uint32_t& r1,uint32_t& r2,uint32_t& r3, uint32_t a){
    asm volatile("ldmatrix.sync.aligned.m8n8.x4.trans.shared.b16 {%0,%1,%2,%3},[%4];"
                 : "=r"(r0),"=r"(r1),"=r"(r2),"=r"(r3) : "r"(a));
}
__device__ __forceinline__ void mma16816h(float* c, const uint32_t* a, uint32_t b0, uint32_t b1){
    asm volatile("mma.sync.aligned.m16n8k16.row.col.f32.f16.f16.f32 "
                 "{%0,%1,%2,%3},{%4,%5,%6,%7},{%8,%9},{%0,%1,%2,%3};"
                 : "+f"(c[0]),"+f"(c[1]),"+f"(c[2]),"+f"(c[3])
                 : "r"(a[0]),"r"(a[1]),"r"(a[2]),"r"(a[3]),"r"(b0),"r"(b1));
}

#define ALD2 40    // Ash row stride (halves), BK=32 + pad 8
#define BLD  136   // Bsh row stride (halves)

template<int K>
__global__ __launch_bounds__(256)
void gemm_mma(int wsel, const float* __restrict__ bias, int osel, int rb0){
    const __half* A  = g_MSG;
    const __half* Wh = (wsel == 0) ? g_W0h : (wsel == 1) ? g_W1h : g_W2h;
    __nv_bfloat16* out = gbuf16(osel);

    __shared__ __half Ash[2][128*ALD2];
    __shared__ __half Bsh[2][32*BLD];

    const int t = threadIdx.x;
    const int warp = t >> 5, lane = t & 31;
    const int wm = warp >> 2, wn = warp & 3;
    const int row0 = (rb0 + blockIdx.y)*128, col0 = blockIdx.x*128;

    float acc[4][4][4];
    #pragma unroll
    for (int i=0;i<4;i++)
        #pragma unroll
        for (int j=0;j<4;j++)
            #pragma unroll
            for (int q=0;q<4;q++) acc[i][j][q]=0.f;

    auto prefetch = [&](int ks, int buf){
        const int k0 = ks*32;
        #pragma unroll
        for (int s=0;s<2;s++){
            int c = t + s*256;
            int r = c >> 2, seg = c & 3;
            int gr = row0 + r;
            uint32_t dst = sptr(&Ash[buf][r*ALD2 + seg*8]);
            const void* src = A + (size_t)gr*K + k0 + seg*8;
            cpa16(dst, src, (gr < NN) ? 16 : 0);
        }
        #pragma unroll
        for (int s=0;s<2;s++){
            int c = t + s*256;
            int r = c >> 4, seg = c & 15;
            uint32_t dst = sptr(&Bsh[buf][r*BLD + seg*8]);
            const void* src = Wh + (size_t)(k0 + r)*HID + col0 + seg*8;
            cpa16(dst, src, 16);
        }
    };

    auto compute = [&](int buf){
        #pragma unroll
        for (int h=0; h<2; h++){
            const int arow = wm*64 + (lane & 15);
            const int acol = h*16 + (lane >> 4)*8;
            uint32_t aA = sptr(&Ash[buf][0]) + (uint32_t)((arow*ALD2 + acol)*2);
            const int brow = h*16 + (lane & 15);
            const int bcol = wn*32 + (lane >> 4)*8;
            uint32_t bA = sptr(&Bsh[buf][0]) + (uint32_t)((brow*BLD + bcol)*2);

            uint32_t A_[4][4], B[4][2];
            #pragma unroll
            for (int mi=0; mi<4; mi++)
                ldsm4(A_[mi][0],A_[mi][1],A_[mi][2],A_[mi][3], aA + (uint32_t)(mi*16*ALD2*2));
            #pragma unroll
            for (int np=0; np<2; np++)
                ldsm4t(B[2*np][0],B[2*np][1],B[2*np+1][0],B[2*np+1][1],
                       bA + (uint32_t)(np*16*2));
            #pragma unroll
            for (int mi=0; mi<4; mi++)
                #pragma unroll
                for (int ni=0; ni<4; ni++)
                    mma16816h(acc[mi][ni], A_[mi], B[ni][0], B[ni][1]);
        }
    };

    const int KS = K/32;
    prefetch(0, 0); CP_COMMIT();
    int buf = 0;
    for (int ks=0; ks<KS; ks++){
        CP_WAIT0();
        __syncthreads();
        if (ks+1 < KS){ prefetch(ks+1, buf^1); CP_COMMIT(); }
        compute(buf);
        buf ^= 1;
    }

    const int gid = lane >> 2, tig = lane & 3;
    #pragma unroll
    for (int ni=0; ni<4; ni++){
        int c = col0 + wn*32 + ni*8 + tig*2;
        float2 bb = *(const float2*)(bias + c);
        #pragma unroll
        for (int mi=0; mi<4; mi++){
            int r = row0 + wm*64 + mi*16 + gid;
            if (r < NN){
                __nv_bfloat162 o = __floats2bfloat162_rn(
                    fmaxf(acc[mi][ni][0] + bb.x, 0.f),
                    fmaxf(acc[mi][ni][1] + bb.y, 0.f));
                *(__nv_bfloat162*)(out + (size_t)r*HID + c) = o;
            }
            int r2 = r + 8;
            if (r2 < NN){
                __nv_bfloat162 o = __floats2bfloat162_rn(
                    fmaxf(acc[mi][ni][2] + bb.x, 0.f),
                    fmaxf(acc[mi][ni][3] + bb.y, 0.f));
                *(__nv_bfloat162*)(out + (size_t)r2*HID + c) = o;
            }
        }
    }
}

// ---------------- multipool (bf16 input) + output zeroing ----------------
__global__ void pool_kernel(const int* __restrict__ batches, float* out){
    const __nv_bfloat16* h = g_BA;
    __shared__ int idxs[SUBSZ];
    int t = threadIdx.x, b = blockIdx.x;
    if (b == 0 && t == 0) out[0] = 0.f;
    if (t < SUBSZ) idxs[t] = batches[b*SUBSZ + t];
    __syncthreads();
    float s = 0.f, mn = 3.4e38f, mx = -3.4e38f;
    #pragma unroll 8
    for (int m = 0; m < SUBSZ; m++){
        float v = __bfloat162float(h[(size_t)idxs[m]*HID + t]);
        s += v; mn = fminf(mn, v); mx = fmaxf(mx, v);
    }
    float* z = g_Z + (size_t)b*4*HID;
    z[t]         = s;
    z[HID + t]   = s * (1.0f/SUBSZ);
    z[2*HID + t] = mn;
    z[3*HID + t] = mx;
}

// ---------------- readout + BCE ----------------
__global__ __launch_bounds__(256)
void readout8(const float* __restrict__ Wr1, const float* __restrict__ br1,
              const float* __restrict__ Wr2, const float* __restrict__ br2,
              const float* __restrict__ labels, float* out){
    const int b0 = blockIdx.x*8;
    __shared__ float z[8*4*HID];
    int t = threadIdx.x;
    const float4* zg = (const float4*)(g_Z + (size_t)b0*4*HID);
    #pragma unroll
    for (int j = t; j < 8*4*HID/4; j += 256)
        ((float4*)z)[j] = zg[j];
    __syncthreads();

    float bb = br1[t];
    float acc[8];
    #pragma unroll
    for (int j=0;j<8;j++) acc[j] = bb;

    #pragma unroll 8
    for (int k=0;k<4*HID;k++){
        float w = Wr1[(size_t)k*HID + t];
        #pragma unroll
        for (int j=0;j<8;j++) acc[j] += z[j*4*HID + k]*w;
    }
    __syncthreads();
    float wr2 = Wr2[t];
    #pragma unroll
    for (int j=0;j<8;j++) z[j*HID + t] = fmaxf(acc[j], 0.f)*wr2;
    __syncthreads();

    int w = t >> 5, lane = t & 31;
    float s = 0.f;
    #pragma unroll
    for (int q=0;q<8;q++) s += z[w*HID + lane + q*32];
    #pragma unroll
    for (int off=16; off>0; off>>=1) s += __shfl_xor_sync(0xffffffffu, s, off);
    if (lane == 0){
        float p = s + br2[0];
        float l = labels[b0 + w];
        float term = fmaxf(p, 0.f) - p*l + log1pf(expf(-fabsf(p)));
        atomicAdd(out, term * (1.0f/NSUB));
    }
}

// ---------------- launch ----------------
static cudaStream_t g_s2 = nullptr;
static cudaEvent_t  g_evFork = nullptr, g_evJoin = nullptr;
static cudaEvent_t  g_evG[3] = {nullptr,nullptr,nullptr};
static cudaEvent_t  g_evM[3] = {nullptr,nullptr,nullptr};

extern "C" void kernel_launch(void* const* d_in, const int* in_sizes, int n_in,
                              void* d_out, int out_size){
    const float* x       = (const float*)d_in[0];
    const int*   esrc    = (const int*)  d_in[1];
    const int*   edst    = (const int*)  d_in[2];
    const float* ew      = (const float*)d_in[3];
    const int*   batches = (const int*)  d_in[4];
    const float* labels  = (const float*)d_in[6];
    const float* W0      = (const float*)d_in[7];
    const float* b0      = (const float*)d_in[8];
    const float* W1      = (const float*)d_in[9];
    const float* b1      = (const float*)d_in[10];
    const float* W2      = (const float*)d_in[11];
    const float* b2      = (const float*)d_in[12];
    const float* eps     = (const float*)d_in[13];
    const float* Wr1     = (const float*)d_in[14];
    const float* br1     = (const float*)d_in[15];
    const float* Wr2     = (const float*)d_in[16];
    const float* br2     = (const float*)d_in[17];
    float* out = (float*)d_out;

    if (!g_s2){
        cudaStreamCreateWithFlags(&g_s2, cudaStreamNonBlocking);
        cudaEventCreateWithFlags(&g_evFork, cudaEventDisableTiming);
        cudaEventCreateWithFlags(&g_evJoin, cudaEventDisableTiming);
        for (int i=0;i<3;i++){
            cudaEventCreateWithFlags(&g_evG[i], cudaEventDisableTiming);
            cudaEventCreateWithFlags(&g_evM[i], cudaEventDisableTiming);
        }
    }

    cudaEventRecord(g_evFork, 0);
    cudaStreamWaitEvent(g_s2, g_evFork, 0);

    // main stream: input prep + weight conversion
    build_h0<<<4096, 256>>>(x);
    scatter_batch<<<(MTOT+255)/256, 256>>>(batches);
    build_w0h<<<(K0*HID+255)/256, 256>>>(W0);
    build_wh<<<(HID*HID+255)/256, 256>>>(W1, 1);
    build_wh<<<(HID*HID+255)/256, 256>>>(W2, 2);

    // side stream: CSR build (by dst)
    zero_degcur<<<(NN+255)/256, 256, 0, g_s2>>>();
    hist_dst<<<(NE+255)/256, 256, 0, g_s2>>>(edst);
    scan_block<<<NBLK, SCAN_B, 0, g_s2>>>();
    scan_bsums<<<1, 256, 0, g_s2>>>();
    scan_add<<<NBLK, SCAN_B, 0, g_s2>>>();
    csr_scatter<<<(NE+255)/256, 256, 0, g_s2>>>(esrc, edst, ew);

    cudaEventRecord(g_evJoin, g_s2);
    cudaStreamWaitEvent(0, g_evJoin, 0);

    const int gG1 = (ROWS1+7)/8;           // gather blocks, half 1
    const int gG2 = (NN-ROWS1+7)/8;        // gather blocks, half 2
    dim3 mg1(2, RB1), mg2(2, RB2);

    // per-layer pipelined halves: gather(h2) overlaps gemm(h1)
    struct { int hsel, wsel, osel, w4r, w4p, Ksel; const float* b; } L[3] = {
        {0, 0, 1, 33, 40, 0, b0},
        {1, 1, 2, 64, 64, 1, b1},
        {2, 2, 1, 64, 64, 1, b2},
    };
    for (int i=0;i<3;i++){
        int ld = L[i].Ksel ? HID : K0;
        // half-1 gather on main stream
        if (L[i].Ksel)
            csr_gather<<<gG1, 256>>>(L[i].hsel, eps, i, HID, 64, 64, 0, ROWS1);
        else
            csr_gather<<<gG1, 256>>>(0, eps, 0, K0, 33, 40, 0, ROWS1);
        cudaEventRecord(g_evG[i], 0);
        // half-2 gather on main stream
        if (L[i].Ksel)
            csr_gather<<<gG2, 256>>>(L[i].hsel, eps, i, HID, 64, 64, ROWS1, NN);
        else
            csr_gather<<<gG2, 256>>>(0, eps, 0, K0, 33, 40, ROWS1, NN);
        // half-1 gemm on side stream (waits only on half-1 gather)
        cudaStreamWaitEvent(g_s2, g_evG[i], 0);
        if (L[i].Ksel)
            gemm_mma<HID><<<mg1, 256, 0, g_s2>>>(L[i].wsel, L[i].b, L[i].osel, 0);
        else
            gemm_mma<K0><<<mg1, 256, 0, g_s2>>>(0, b0, 1, 0);
        cudaEventRecord(g_evM[i], g_s2);
        // half-2 gemm on main stream (in-order after half-2 gather)
        if (L[i].Ksel)
            gemm_mma<HID><<<mg2, 256>>>(L[i].wsel, L[i].b, L[i].osel, RB1);
        else
            gemm_mma<K0><<<mg2, 256>>>(0, b0, 1, RB1);
        // join: next layer (or pool) must see half-1 gemm output
        cudaStreamWaitEvent(0, g_evM[i], 0);
        (void)ld;
    }

    pool_kernel<<<NSUB, HID>>>(batches, out);
    readout8<<<NSUB/8, 256>>>(Wr1, br1, Wr2, br2, labels, out);
}

// round 15
// speedup vs baseline: 1.0182x; 1.0182x over previous
#include <cuda_runtime.h>
#include <cuda_bf16.h>
#include <cuda_fp16.h>
#include <math.h>
#include <stdint.h>

#define NN    50000
#define FEAT  128
#define HID   256
#define K0    160        // layer-0 K (129 live -> 132 used) padded to 160
#define NE    800000
#define NSUB  512
#define SUBSZ 64
#define MTOT  (NSUB*SUBSZ)

#define SCAN_B 256
#define NBLK   ((NN + SCAN_B - 1) / SCAN_B)   // 196

// ---------------- scratch (device globals; no allocation allowed) ----------------
__device__ __align__(16) __half         g_MSG[NN*HID];   // fp16 GEMM A (160-col view for L0)
__device__ __align__(16) __nv_bfloat16  g_B0 [NN*K0];    // bf16 h0
__device__ __align__(16) __nv_bfloat16  g_BA [NN*HID];   // bf16 h (layers)
__device__ __align__(16) __nv_bfloat16  g_BB [NN*HID];
__device__ __align__(16) __half         g_W0h[K0*HID];   // fp16 zero-padded W0
__device__ __align__(16) __half         g_W1h[HID*HID];
__device__ __align__(16) __half         g_W2h[HID*HID];
__device__ __align__(16) float          g_Z  [NSUB*4*HID];
// CSR scratch
__device__ int   g_deg [NN];
__device__ int   g_cur [NN];
__device__ int   g_off [NN+1];
__device__ int   g_bsum[NBLK];
__device__ int   g_csrc[NE];
__device__ float g_cw  [NE];

__device__ __forceinline__ __nv_bfloat16* gbuf16(int id){
    switch(id){
        case 0: return g_B0;
        case 1: return g_BA;
        default: return g_BB;
    }
}

// ---------------- setup ----------------
__global__ void build_h0(const float* __restrict__ x){
    int idx = blockIdx.x*blockDim.x + threadIdx.x;
    const int total = NN*K0;
    for (; idx < total; idx += gridDim.x*blockDim.x){
        int i = idx / K0;
        int c = idx - i*K0;
        g_B0[idx] = (c < FEAT) ? __float2bfloat16(x[i*FEAT + c]) : __float2bfloat16(0.f);
    }
}

__global__ void scatter_batch(const int* __restrict__ batches){
    int m = blockIdx.x*blockDim.x + threadIdx.x;
    if (m < MTOT) g_B0[(size_t)batches[m]*K0 + FEAT] = __float2bfloat16(1.0f);
}

__global__ void build_w0h(const float* __restrict__ W0){
    int idx = blockIdx.x*blockDim.x + threadIdx.x;
    if (idx < K0*HID){
        int r = idx / HID;
        int c = idx - r*HID;
        g_W0h[idx] = (r < FEAT+1) ? __float2half(W0[r*HID + c]) : __float2half(0.f);
    }
}

__global__ void build_wh(const float* __restrict__ W, int sel){
    __half* dst = (sel == 1) ? g_W1h : g_W2h;
    int i = blockIdx.x*blockDim.x + threadIdx.x;
    if (i < HID*HID) dst[i] = __float2half(W[i]);
}

// ---------------- CSR build ----------------
__global__ void hist_dst(const int* __restrict__ dst){
    int e = blockIdx.x*blockDim.x + threadIdx.x;
    if (e < NE) atomicAdd(&g_deg[dst[e]], 1);
}

__global__ void scan_block(){
    __shared__ int sh[SCAN_B];
    int i = blockIdx.x*SCAN_B + threadIdx.x;
    int v = (i < NN) ? g_deg[i] : 0;
    sh[threadIdx.x] = v;
    __syncthreads();
    #pragma unroll
    for (int off = 1; off < SCAN_B; off <<= 1){
        int add = (threadIdx.x >= off) ? sh[threadIdx.x - off] : 0;
        __syncthreads();
        sh[threadIdx.x] += add;
        __syncthreads();
    }
    if (i < NN) g_off[i] = sh[threadIdx.x] - v;
    if (threadIdx.x == SCAN_B-1) g_bsum[blockIdx.x] = sh[SCAN_B-1];
}

__global__ void scan_bsums(){
    __shared__ int sh[256];
    int t = threadIdx.x;
    int v = (t < NBLK) ? g_bsum[t] : 0;
    sh[t] = v;
    __syncthreads();
    #pragma unroll
    for (int off = 1; off < 256; off <<= 1){
        int add = (t >= off) ? sh[t - off] : 0;
        __syncthreads();
        sh[t] += add;
        __syncthreads();
    }
    if (t < NBLK) g_bsum[t] = sh[t] - v;
}

__global__ void scan_add(){
    int i = blockIdx.x*SCAN_B + threadIdx.x;
    if (i < NN) g_off[i] += g_bsum[blockIdx.x];
    if (i == 0) g_off[NN] = NE;
}

__global__ void csr_scatter(const int* __restrict__ src, const int* __restrict__ dst,
                            const float* __restrict__ ew){
    int e = blockIdx.x*blockDim.x + threadIdx.x;
    if (e < NE){
        int d = dst[e];
        int pos = g_off[d] + atomicAdd(&g_cur[d], 1);
        g_csrc[pos] = src[e];
        g_cw[pos]   = ew[e];
    }
}

// ---------------- gather (bf16 inputs, f32 accumulate, fp16 output) ----------------
__device__ __forceinline__ void facc(float4& a, float w, uint2 u){
    float2 f0 = __bfloat1622float2(*(__nv_bfloat162*)&u.x);
    float2 f1 = __bfloat1622float2(*(__nv_bfloat162*)&u.y);
    a.x += w*f0.x; a.y += w*f0.y; a.z += w*f1.x; a.w += w*f1.y;
}
__device__ __forceinline__ uint2 f4toh4(float4 a){
    __half2 lo = __floats2half2_rn(a.x, a.y);
    __half2 hi = __floats2half2_rn(a.z, a.w);
    return make_uint2(*(uint32_t*)&lo, *(uint32_t*)&hi);
}

__global__ __launch_bounds__(256)
void csr_gather(int hsel, const float* __restrict__ eps, int ei, int ld, int w4r, int w4p){
    const __nv_bfloat16* h = gbuf16(hsel);
    int n = blockIdx.x*8 + (threadIdx.x >> 5);
    if (n >= NN) return;
    int lane = threadIdx.x & 31;
    int s0 = g_off[n], s1 = g_off[n+1];

    const bool a0 = (lane      < w4r);
    const bool a1 = (lane + 32 < w4r);
    float4 acc0 = make_float4(0.f,0.f,0.f,0.f);
    float4 acc1 = make_float4(0.f,0.f,0.f,0.f);

    int e = s0;
    for (; e + 4 <= s1; e += 4){
        int   si[4]; float wi[4];
        #pragma unroll
        for (int j=0;j<4;j++){
            si[j] = __ldg(&g_csrc[e+j]);
            wi[j] = __ldg(&g_cw[e+j]);
        }
        uint2 u0[4], u1[4];
        #pragma unroll
        for (int j=0;j<4;j++){
            const uint2* hs = (const uint2*)(h + (size_t)si[j]*ld);
            if (a0) u0[j] = __ldg(&hs[lane]);
            if (a1) u1[j] = __ldg(&hs[lane+32]);
        }
        #pragma unroll
        for (int j=0;j<4;j++){
            if (a0) facc(acc0, wi[j], u0[j]);
            if (a1) facc(acc1, wi[j], u1[j]);
        }
    }
    for (; e < s1; e++){
        int   s = __ldg(&g_csrc[e]);
        float w = __ldg(&g_cw[e]);
        const uint2* hs = (const uint2*)(h + (size_t)s*ld);
        if (a0){ uint2 u = __ldg(&hs[lane]);    facc(acc0, w, u); }
        if (a1){ uint2 u = __ldg(&hs[lane+32]); facc(acc1, w, u); }
    }

    const float ep = 1.0f + eps[ei];
    const uint2* hn = (const uint2*)(h + (size_t)n*ld);
    uint2* mrow = (uint2*)(g_MSG + (size_t)n*ld);
    if (a0){
        uint2 u = __ldg(&hn[lane]);
        facc(acc0, ep, u);
        mrow[lane] = f4toh4(acc0);
    }
    if (a1){
        uint2 u = __ldg(&hn[lane+32]);
        facc(acc1, ep, u);
        mrow[lane+32] = f4toh4(acc1);
    } else if (lane + 32 < w4p){
        mrow[lane+32] = make_uint2(0u, 0u);
    }
}

// ---------------- tensor-core GIN GEMM: outb16 = relu(MSG @ W + b) ------
// pure fp16, BK=32, cp.async double-buffered, 1 sync per kstep.
__device__ __forceinline__ uint32_t sptr(const void* p){
    return (uint32_t)__cvta_generic_to_shared(p);
}
__device__ __forceinline__ void cpa16(uint32_t smem, const void* g, int nbytes){
    asm volatile("cp.async.cg.shared.global [%0], [%1], 16, %2;"
                 :: "r"(smem), "l"(g), "r"(nbytes) : "memory");
}
#define CP_COMMIT() asm volatile("cp.async.commit_group;" ::: "memory")
#define CP_WAIT0()  asm volatile("cp.async.wait_group 0;" ::: "memory")

__device__ __forceinline__ void ldsm4(uint32_t& r0,uint32_t& r1,uint32_t& r2,uint32_t& r3, uint32_t a){
    asm volatile("ldmatrix.sync.aligned.m8n8.x4.shared.b16 {%0,%1,%2,%3},[%4];"
                 : "=r"(r0),"=r"(r1),"=r"(r2),"=r"(r3) : "r"(a));
}
__device__ __forceinline__ void ldsm4t(uint32_t& r0,uint32_t& r1,uint32_t& r2,uint32_t& r3, uint32_t a){
    asm volatile("ldmatrix.sync.aligned.m8n8.x4.trans.shared.b16 {%0,%1,%2,%3},[%4];"
                 : "=r"(r0),"=r"(r1),"=r"(r2),"=r"(r3) : "r"(a));
}
__device__ __forceinline__ void mma16816h(float* c, const uint32_t* a, uint32_t b0, uint32_t b1){
    asm volatile("mma.sync.aligned.m16n8k16.row.col.f32.f16.f16.f32 "
                 "{%0,%1,%2,%3},{%4,%5,%6,%7},{%8,%9},{%0,%1,%2,%3};"
                 : "+f"(c[0]),"+f"(c[1]),"+f"(c[2]),"+f"(c[3])
                 : "r"(a[0]),"r"(a[1]),"r"(a[2]),"r"(a[3]),"r"(b0),"r"(b1));
}

#define ALD2 40    // Ash row stride (halves), BK=32 + pad 8
#define BLD  136   // Bsh row stride (halves)

template<int K>
__global__ __launch_bounds__(256)
void gemm_mma(int wsel, const float* __restrict__ bias, int osel){
    const __half* A  = g_MSG;
    const __half* Wh = (wsel == 0) ? g_W0h : (wsel == 1) ? g_W1h : g_W2h;
    __nv_bfloat16* out = gbuf16(osel);

    __shared__ __half Ash[2][128*ALD2];
    __shared__ __half Bsh[2][32*BLD];

    const int t = threadIdx.x;
    const int warp = t >> 5, lane = t & 31;
    const int wm = warp >> 2, wn = warp & 3;
    const int row0 = blockIdx.y*128, col0 = blockIdx.x*128;

    float acc[4][4][4];
    #pragma unroll
    for (int i=0;i<4;i++)
        #pragma unroll
        for (int j=0;j<4;j++)
            #pragma unroll
            for (int q=0;q<4;q++) acc[i][j][q]=0.f;

    auto prefetch = [&](int ks, int buf){
        const int k0 = ks*32;
        #pragma unroll
        for (int s=0;s<2;s++){
            int c = t + s*256;
            int r = c >> 2, seg = c & 3;
            int gr = row0 + r;
            uint32_t dst = sptr(&Ash[buf][r*ALD2 + seg*8]);
            const void* src = A + (size_t)gr*K + k0 + seg*8;
            cpa16(dst, src, (gr < NN) ? 16 : 0);
        }
        #pragma unroll
        for (int s=0;s<2;s++){
            int c = t + s*256;
            int r = c >> 4, seg = c & 15;
            uint32_t dst = sptr(&Bsh[buf][r*BLD + seg*8]);
            const void* src = Wh + (size_t)(k0 + r)*HID + col0 + seg*8;
            cpa16(dst, src, 16);
        }
    };

    auto compute = [&](int buf){
        #pragma unroll
        for (int h=0; h<2; h++){
            const int arow = wm*64 + (lane & 15);
            const int acol = h*16 + (lane >> 4)*8;
            uint32_t aA = sptr(&Ash[buf][0]) + (uint32_t)((arow*ALD2 + acol)*2);
            const int brow = h*16 + (lane & 15);
            const int bcol = wn*32 + (lane >> 4)*8;
            uint32_t bA = sptr(&Bsh[buf][0]) + (uint32_t)((brow*BLD + bcol)*2);

            uint32_t A_[4][4], B[4][2];
            #pragma unroll
            for (int mi=0; mi<4; mi++)
                ldsm4(A_[mi][0],A_[mi][1],A_[mi][2],A_[mi][3], aA + (uint32_t)(mi*16*ALD2*2));
            #pragma unroll
            for (int np=0; np<2; np++)
                ldsm4t(B[2*np][0],B[2*np][1],B[2*np+1][0],B[2*np+1][1],
                       bA + (uint32_t)(np*16*2));
            #pragma unroll
            for (int mi=0; mi<4; mi++)
                #pragma unroll
                for (int ni=0; ni<4; ni++)
                    mma16816h(acc[mi][ni], A_[mi], B[ni][0], B[ni][1]);
        }
    };

    const int KS = K/32;
    prefetch(0, 0); CP_COMMIT();
    int buf = 0;
    for (int ks=0; ks<KS; ks++){
        CP_WAIT0();
        __syncthreads();
        if (ks+1 < KS){ prefetch(ks+1, buf^1); CP_COMMIT(); }
        compute(buf);
        buf ^= 1;
    }

    // epilogue: bias + relu, bf16 stores
    const int gid = lane >> 2, tig = lane & 3;
    #pragma unroll
    for (int ni=0; ni<4; ni++){
        int c = col0 + wn*32 + ni*8 + tig*2;
        float2 bb = *(const float2*)(bias + c);
        #pragma unroll
        for (int mi=0; mi<4; mi++){
            int r = row0 + wm*64 + mi*16 + gid;
            if (r < NN){
                __nv_bfloat162 o = __floats2bfloat162_rn(
                    fmaxf(acc[mi][ni][0] + bb.x, 0.f),
                    fmaxf(acc[mi][ni][1] + bb.y, 0.f));
                *(__nv_bfloat162*)(out + (size_t)r*HID + c) = o;
            }
            int r2 = r + 8;
            if (r2 < NN){
                __nv_bfloat162 o = __floats2bfloat162_rn(
                    fmaxf(acc[mi][ni][2] + bb.x, 0.f),
                    fmaxf(acc[mi][ni][3] + bb.y, 0.f));
                *(__nv_bfloat162*)(out + (size_t)r2*HID + c) = o;
            }
        }
    }
}

// ---------------- multipool (bf16 input) + output zeroing ----------------
__global__ void pool_kernel(const int* __restrict__ batches, float* out){
    const __nv_bfloat16* h = g_BA;   // final layer output
    __shared__ int idxs[SUBSZ];
    int t = threadIdx.x, b = blockIdx.x;
    if (b == 0 && t == 0) out[0] = 0.f;   // pool fully precedes readout; race-free
    if (t < SUBSZ) idxs[t] = batches[b*SUBSZ + t];
    __syncthreads();
    float s = 0.f, mn = 3.4e38f, mx = -3.4e38f;
    #pragma unroll 8
    for (int m = 0; m < SUBSZ; m++){
        float v = __bfloat162float(h[(size_t)idxs[m]*HID + t]);
        s += v; mn = fminf(mn, v); mx = fmaxf(mx, v);
    }
    float* z = g_Z + (size_t)b*4*HID;
    z[t]         = s;
    z[HID + t]   = s * (1.0f/SUBSZ);
    z[2*HID + t] = mn;
    z[3*HID + t] = mx;
}

// ---------------- readout + BCE ----------------
__global__ __launch_bounds__(256)
void readout8(const float* __restrict__ Wr1, const float* __restrict__ br1,
              const float* __restrict__ Wr2, const float* __restrict__ br2,
              const float* __restrict__ labels, float* out){
    const int b0 = blockIdx.x*8;
    __shared__ float z[8*4*HID];
    int t = threadIdx.x;
    const float4* zg = (const float4*)(g_Z + (size_t)b0*4*HID);
    #pragma unroll
    for (int j = t; j < 8*4*HID/4; j += 256)
        ((float4*)z)[j] = zg[j];
    __syncthreads();

    float bb = br1[t];
    float acc[8];
    #pragma unroll
    for (int j=0;j<8;j++) acc[j] = bb;

    #pragma unroll 8
    for (int k=0;k<4*HID;k++){
        float w = Wr1[(size_t)k*HID + t];
        #pragma unroll
        for (int j=0;j<8;j++) acc[j] += z[j*4*HID + k]*w;
    }
    __syncthreads();
    float wr2 = Wr2[t];
    #pragma unroll
    for (int j=0;j<8;j++) z[j*HID + t] = fmaxf(acc[j], 0.f)*wr2;
    __syncthreads();

    int w = t >> 5, lane = t & 31;
    float s = 0.f;
    #pragma unroll
    for (int q=0;q<8;q++) s += z[w*HID + lane + q*32];
    #pragma unroll
    for (int off=16; off>0; off>>=1) s += __shfl_xor_sync(0xffffffffu, s, off);
    if (lane == 0){
        float p = s + br2[0];
        float l = labels[b0 + w];
        float term = fmaxf(p, 0.f) - p*l + log1pf(expf(-fabsf(p)));
        atomicAdd(out, term * (1.0f/NSUB));
    }
}

// ---------------- launch ----------------
static cudaStream_t g_s2 = nullptr;
static cudaEvent_t  g_evFork = nullptr, g_evJoin = nullptr;
static void* g_degPtr = nullptr;
static void* g_curPtr = nullptr;

extern "C" void kernel_launch(void* const* d_in, const int* in_sizes, int n_in,
                              void* d_out, int out_size){
    const float* x       = (const float*)d_in[0];
    const int*   esrc    = (const int*)  d_in[1];
    const int*   edst    = (const int*)  d_in[2];
    const float* ew      = (const float*)d_in[3];
    const int*   batches = (const int*)  d_in[4];
    const float* labels  = (const float*)d_in[6];
    const float* W0      = (const float*)d_in[7];
    const float* b0      = (const float*)d_in[8];
    const float* W1      = (const float*)d_in[9];
    const float* b1      = (const float*)d_in[10];
    const float* W2      = (const float*)d_in[11];
    const float* b2      = (const float*)d_in[12];
    const float* eps     = (const float*)d_in[13];
    const float* Wr1     = (const float*)d_in[14];
    const float* br1     = (const float*)d_in[15];
    const float* Wr2     = (const float*)d_in[16];
    const float* br2     = (const float*)d_in[17];
    float* out = (float*)d_out;

    if (!g_s2){
        cudaStreamCreateWithFlags(&g_s2, cudaStreamNonBlocking);
        cudaEventCreateWithFlags(&g_evFork, cudaEventDisableTiming);
        cudaEventCreateWithFlags(&g_evJoin, cudaEventDisableTiming);
        cudaGetSymbolAddress(&g_degPtr, g_deg);
        cudaGetSymbolAddress(&g_curPtr, g_cur);
    }

    cudaEventRecord(g_evFork, 0);
    cudaStreamWaitEvent(g_s2, g_evFork, 0);

    // main stream: input prep + weight conversion
    build_h0<<<4096, 256>>>(x);
    scatter_batch<<<(MTOT+255)/256, 256>>>(batches);
    build_w0h<<<(K0*HID+255)/256, 256>>>(W0);
    build_wh<<<(HID*HID+255)/256, 256>>>(W1, 1);
    build_wh<<<(HID*HID+255)/256, 256>>>(W2, 2);

    // side stream: CSR build (by dst)
    cudaMemsetAsync(g_degPtr, 0, NN*sizeof(int), g_s2);
    cudaMemsetAsync(g_curPtr, 0, NN*sizeof(int), g_s2);
    hist_dst<<<(NE+255)/256, 256, 0, g_s2>>>(edst);
    scan_block<<<NBLK, SCAN_B, 0, g_s2>>>();
    scan_bsums<<<1, 256, 0, g_s2>>>();
    scan_add<<<NBLK, SCAN_B, 0, g_s2>>>();
    csr_scatter<<<(NE+255)/256, 256, 0, g_s2>>>(esrc, edst, ew);

    cudaEventRecord(g_evJoin, g_s2);
    cudaStreamWaitEvent(0, g_evJoin, 0);

    dim3 gemmGrid(2, (NN+127)/128);
    const int gatherGrid = (NN+7)/8;

    // layer 0
    csr_gather<<<gatherGrid, 256>>>(0, eps, 0, K0, 33, 40);
    gemm_mma<K0><<<gemmGrid, 256>>>(0, b0, 1);

    // layer 1
    csr_gather<<<gatherGrid, 256>>>(1, eps, 1, HID, 64, 64);
    gemm_mma<HID><<<gemmGrid, 256>>>(1, b1, 2);

    // layer 2
    csr_gather<<<gatherGrid, 256>>>(2, eps, 2, HID, 64, 64);
    gemm_mma<HID><<<gemmGrid, 256>>>(2, b2, 1);

    pool_kernel<<<NSUB, HID>>>(batches, out);
    readout8<<<NSUB/8, 256>>>(Wr1, br1, Wr2, br2, labels, out);
}

// round 17
// speedup vs baseline: 1.1064x; 1.0866x over previous
#include <cuda_runtime.h>
#include <cuda_bf16.h>
#include <cuda_fp16.h>
#include <math.h>
#include <stdint.h>

#define NN    50000
#define FEAT  128
#define HID   256
#define K0    160        // layer-0 K (129 live -> 132 used) padded to 160
#define NE    800000
#define NSUB  512
#define SUBSZ 64
#define MTOT  (NSUB*SUBSZ)

#define SCAN_B 256
#define NBLK   ((NN + SCAN_B - 1) / SCAN_B)   // 196

// ---------------- scratch (device globals; no allocation allowed) ----------------
__device__ __align__(16) __half         g_MSG[NN*HID];   // fp16 GEMM A (160-col view for L0)
__device__ __align__(16) __nv_bfloat16  g_B0 [NN*K0];    // bf16 h0
__device__ __align__(16) __nv_bfloat16  g_BA [NN*HID];   // bf16 h (layers; L2 output dense)
__device__ __align__(16) __nv_bfloat16  g_BB [NN*HID];
__device__ __align__(16) __half         g_W0h[K0*HID];
__device__ __align__(16) __half         g_W1h[HID*HID];
__device__ __align__(16) __half         g_W2h[HID*HID];
__device__ __align__(16) float          g_Z  [NSUB*4*HID];
// CSR scratch
__device__ int   g_deg [NN];
__device__ int   g_cur [NN];
__device__ int   g_off [NN+1];
__device__ int   g_bsum[NBLK];
__device__ int   g_csrc[NE];
__device__ float g_cw  [NE];
// marked-node compaction (layer 2 only computes these rows)
__device__ int   g_mark  [NN];
__device__ int   g_midx  [NN];
__device__ int   g_bsum2 [NBLK];
__device__ int   g_list  [NN];
__device__ int   g_mapidx[NN];
__device__ int   g_cnt;

__device__ __forceinline__ __nv_bfloat16* gbuf16(int id){
    switch(id){
        case 0: return g_B0;
        case 1: return g_BA;
        default: return g_BB;
    }
}

// ---------------- setup ----------------
__global__ void build_h0(const float* __restrict__ x){
    int idx = blockIdx.x*blockDim.x + threadIdx.x;
    const int total = NN*K0;
    for (; idx < total; idx += gridDim.x*blockDim.x){
        int i = idx / K0;
        int c = idx - i*K0;
        g_B0[idx] = (c < FEAT) ? __float2bfloat16(x[i*FEAT + c]) : __float2bfloat16(0.f);
    }
}

__global__ void scatter_batch(const int* __restrict__ batches){
    int m = blockIdx.x*blockDim.x + threadIdx.x;
    if (m < MTOT) g_B0[(size_t)batches[m]*K0 + FEAT] = __float2bfloat16(1.0f);
}

__global__ void build_w0h(const float* __restrict__ W0){
    int idx = blockIdx.x*blockDim.x + threadIdx.x;
    if (idx < K0*HID){
        int r = idx / HID;
        int c = idx - r*HID;
        g_W0h[idx] = (r < FEAT+1) ? __float2half(W0[r*HID + c]) : __float2half(0.f);
    }
}

__global__ void build_wh(const float* __restrict__ W, int sel){
    __half* dst = (sel == 1) ? g_W1h : g_W2h;
    int i = blockIdx.x*blockDim.x + threadIdx.x;
    if (i < HID*HID) dst[i] = __float2half(W[i]);
}

// ---------------- exclusive scans over NN ints (selector-based; no host symbol UB) ----
// sel 0: in=g_deg,  out=g_off,  bsum=g_bsum   (CSR offsets)
// sel 1: in=g_mark, out=g_midx, bsum=g_bsum2  (compaction indices)
__global__ void scan_block_s(int sel){
    const int* in = (sel == 0) ? g_deg : g_mark;
    int* outE     = (sel == 0) ? g_off : g_midx;
    int* bsum     = (sel == 0) ? g_bsum : g_bsum2;
    __shared__ int sh[SCAN_B];
    int i = blockIdx.x*SCAN_B + threadIdx.x;
    int v = (i < NN) ? in[i] : 0;
    sh[threadIdx.x] = v;
    __syncthreads();
    #pragma unroll
    for (int off = 1; off < SCAN_B; off <<= 1){
        int add = (threadIdx.x >= off) ? sh[threadIdx.x - off] : 0;
        __syncthreads();
        sh[threadIdx.x] += add;
        __syncthreads();
    }
    if (i < NN) outE[i] = sh[threadIdx.x] - v;
    if (threadIdx.x == SCAN_B-1) bsum[blockIdx.x] = sh[SCAN_B-1];
}

__global__ void scan_bsums_s(int sel){
    int* bsum = (sel == 0) ? g_bsum : g_bsum2;
    __shared__ int sh[256];
    int t = threadIdx.x;
    int v = (t < NBLK) ? bsum[t] : 0;
    sh[t] = v;
    __syncthreads();
    #pragma unroll
    for (int off = 1; off < 256; off <<= 1){
        int add = (t >= off) ? sh[t - off] : 0;
        __syncthreads();
        sh[t] += add;
        __syncthreads();
    }
    if (t < NBLK) bsum[t] = sh[t] - v;
}

__global__ void scan_add_s(int sel){
    int* outE       = (sel == 0) ? g_off : g_midx;
    const int* bsum = (sel == 0) ? g_bsum : g_bsum2;
    int i = blockIdx.x*SCAN_B + threadIdx.x;
    if (i < NN) outE[i] += bsum[blockIdx.x];
    if (sel == 0 && i == 0) g_off[NN] = NE;
}

// ---------------- CSR build ----------------
__global__ void hist_dst(const int* __restrict__ dst){
    int e = blockIdx.x*blockDim.x + threadIdx.x;
    if (e < NE) atomicAdd(&g_deg[dst[e]], 1);
}

__global__ void csr_scatter(const int* __restrict__ src, const int* __restrict__ dst,
                            const float* __restrict__ ew){
    int e = blockIdx.x*blockDim.x + threadIdx.x;
    if (e < NE){
        int d = dst[e];
        int pos = g_off[d] + atomicAdd(&g_cur[d], 1);
        g_csrc[pos] = src[e];
        g_cw[pos]   = ew[e];
    }
}

// ---------------- marked-node list ----------------
__global__ void mark_nodes(const int* __restrict__ batches){
    int m = blockIdx.x*blockDim.x + threadIdx.x;
    if (m < MTOT) g_mark[batches[m]] = 1;
}

__global__ void list_build(){
    int n = blockIdx.x*blockDim.x + threadIdx.x;
    if (n < NN){
        int mk = g_mark[n], ix = g_midx[n];
        if (mk) g_list[ix] = n;
        g_mapidx[n] = ix;
        if (n == NN-1) g_cnt = ix + mk;
    }
}

// ---------------- gather helpers ----------------
__device__ __forceinline__ void facc(float4& a, float w, uint2 u){
    float2 f0 = __bfloat1622float2(*(__nv_bfloat162*)&u.x);
    float2 f1 = __bfloat1622float2(*(__nv_bfloat162*)&u.y);
    a.x += w*f0.x; a.y += w*f0.y; a.z += w*f1.x; a.w += w*f1.y;
}
__device__ __forceinline__ uint2 f4toh4(float4 a){
    __half2 lo = __floats2half2_rn(a.x, a.y);
    __half2 hi = __floats2half2_rn(a.z, a.w);
    return make_uint2(*(uint32_t*)&lo, *(uint32_t*)&hi);
}

// full gather (layers 0,1): MSG[n] = (1+eps)h[n] + sum w*h[src]
__global__ __launch_bounds__(256)
void csr_gather(int hsel, const float* __restrict__ eps, int ei, int ld, int w4r, int w4p){
    const __nv_bfloat16* h = gbuf16(hsel);
    int n = blockIdx.x*8 + (threadIdx.x >> 5);
    if (n >= NN) return;
    int lane = threadIdx.x & 31;
    int s0 = g_off[n], s1 = g_off[n+1];

    const bool a0 = (lane      < w4r);
    const bool a1 = (lane + 32 < w4r);
    float4 acc0 = make_float4(0.f,0.f,0.f,0.f);
    float4 acc1 = make_float4(0.f,0.f,0.f,0.f);

    int e = s0;
    for (; e + 4 <= s1; e += 4){
        int   si[4]; float wi[4];
        #pragma unroll
        for (int j=0;j<4;j++){
            si[j] = __ldg(&g_csrc[e+j]);
            wi[j] = __ldg(&g_cw[e+j]);
        }
        uint2 u0[4], u1[4];
        #pragma unroll
        for (int j=0;j<4;j++){
            const uint2* hs = (const uint2*)(h + (size_t)si[j]*ld);
            if (a0) u0[j] = __ldg(&hs[lane]);
            if (a1) u1[j] = __ldg(&hs[lane+32]);
        }
        #pragma unroll
        for (int j=0;j<4;j++){
            if (a0) facc(acc0, wi[j], u0[j]);
            if (a1) facc(acc1, wi[j], u1[j]);
        }
    }
    for (; e < s1; e++){
        int   s = __ldg(&g_csrc[e]);
        float w = __ldg(&g_cw[e]);
        const uint2* hs = (const uint2*)(h + (size_t)s*ld);
        if (a0){ uint2 u = __ldg(&hs[lane]);    facc(acc0, w, u); }
        if (a1){ uint2 u = __ldg(&hs[lane+32]); facc(acc1, w, u); }
    }

    const float ep = 1.0f + eps[ei];
    const uint2* hn = (const uint2*)(h + (size_t)n*ld);
    uint2* mrow = (uint2*)(g_MSG + (size_t)n*ld);
    if (a0){
        uint2 u = __ldg(&hn[lane]);
        facc(acc0, ep, u);
        mrow[lane] = f4toh4(acc0);
    }
    if (a1){
        uint2 u = __ldg(&hn[lane+32]);
        facc(acc1, ep, u);
        mrow[lane+32] = f4toh4(acc1);
    } else if (lane + 32 < w4p){
        mrow[lane+32] = make_uint2(0u, 0u);
    }
}

// dense gather (layer 2): only marked nodes; MSG row d <- node g_list[d]
__global__ __launch_bounds__(256)
void csr_gather_d(int hsel, const float* __restrict__ eps, int ei){
    const int cnt = g_cnt;
    int d = blockIdx.x*8 + (threadIdx.x >> 5);
    if (d >= cnt) return;
    const __nv_bfloat16* h = gbuf16(hsel);
    int n = g_list[d];
    int lane = threadIdx.x & 31;
    int s0 = g_off[n], s1 = g_off[n+1];

    float4 acc0 = make_float4(0.f,0.f,0.f,0.f);
    float4 acc1 = make_float4(0.f,0.f,0.f,0.f);

    int e = s0;
    for (; e + 4 <= s1; e += 4){
        int   si[4]; float wi[4];
        #pragma unroll
        for (int j=0;j<4;j++){
            si[j] = __ldg(&g_csrc[e+j]);
            wi[j] = __ldg(&g_cw[e+j]);
        }
        uint2 u0[4], u1[4];
        #pragma unroll
        for (int j=0;j<4;j++){
            const uint2* hs = (const uint2*)(h + (size_t)si[j]*HID);
            u0[j] = __ldg(&hs[lane]);
            u1[j] = __ldg(&hs[lane+32]);
        }
        #pragma unroll
        for (int j=0;j<4;j++){
            facc(acc0, wi[j], u0[j]);
            facc(acc1, wi[j], u1[j]);
        }
    }
    for (; e < s1; e++){
        int   s = __ldg(&g_csrc[e]);
        float w = __ldg(&g_cw[e]);
        const uint2* hs = (const uint2*)(h + (size_t)s*HID);
        { uint2 u = __ldg(&hs[lane]);    facc(acc0, w, u); }
        { uint2 u = __ldg(&hs[lane+32]); facc(acc1, w, u); }
    }

    const float ep = 1.0f + eps[ei];
    const uint2* hn = (const uint2*)(h + (size_t)n*HID);
    uint2* mrow = (uint2*)(g_MSG + (size_t)d*HID);
    {
        uint2 u = __ldg(&hn[lane]);
        facc(acc0, ep, u);
        mrow[lane] = f4toh4(acc0);
    }
    {
        uint2 u = __ldg(&hn[lane+32]);
        facc(acc1, ep, u);
        mrow[lane+32] = f4toh4(acc1);
    }
}

// ---------------- tensor-core GIN GEMM ----------------
__device__ __forceinline__ uint32_t sptr(const void* p){
    return (uint32_t)__cvta_generic_to_shared(p);
}
__device__ __forceinline__ void cpa16(uint32_t smem, const void* g, int nbytes){
    asm volatile("cp.async.cg.shared.global [%0], [%1], 16, %2;"
                 :: "r"(smem), "l"(g), "r"(nbytes) : "memory");
}
#define CP_COMMIT() asm volatile("cp.async.commit_group;" ::: "memory")
#define CP_WAIT0()  asm volatile("cp.async.wait_group 0;" ::: "memory")

__device__ __forceinline__ void ldsm4(uint32_t& r0,uint32_t& r1,uint32_t& r2,uint32_t& r3, uint32_t a){
    asm volatile("ldmatrix.sync.aligned.m8n8.x4.shared.b16 {%0,%1,%2,%3},[%4];"
                 : "=r"(r0),"=r"(r1),"=r"(r2),"=r"(r3) : "r"(a));
}
__device__ __forceinline__ void ldsm4t(uint32_t& r0,uint32_t& r1,uint32_t& r2,uint32_t& r3, uint32_t a){
    asm volatile("ldmatrix.sync.aligned.m8n8.x4.trans.shared.b16 {%0,%1,%2,%3},[%4];"
                 : "=r"(r0),"=r"(r1),"=r"(r2),"=r"(r3) : "r"(a));
}
__device__ __forceinline__ void mma16816h(float* c, const uint32_t* a, uint32_t b0, uint32_t b1){
    asm volatile("mma.sync.aligned.m16n8k16.row.col.f32.f16.f16.f32 "
                 "{%0,%1,%2,%3},{%4,%5,%6,%7},{%8,%9},{%0,%1,%2,%3};"
                 : "+f"(c[0]),"+f"(c[1]),"+f"(c[2]),"+f"(c[3])
                 : "r"(a[0]),"r"(a[1]),"r"(a[2]),"r"(a[3]),"r"(b0),"r"(b1));
}

#define ALD2 40
#define BLD  136

template<int K>
__global__ __launch_bounds__(256)
void gemm_mma(int wsel, const float* __restrict__ bias, int osel, int msel){
    const int M = msel ? g_cnt : NN;
    const int row0 = blockIdx.y*128;
    if (row0 >= M) return;   // uniform early-exit (before any sync)
    const int col0 = blockIdx.x*128;

    const __half* A  = g_MSG;
    const __half* Wh = (wsel == 0) ? g_W0h : (wsel == 1) ? g_W1h : g_W2h;
    __nv_bfloat16* out = gbuf16(osel);

    __shared__ __half Ash[2][128*ALD2];
    __shared__ __half Bsh[2][32*BLD];

    const int t = threadIdx.x;
    const int warp = t >> 5, lane = t & 31;
    const int wm = warp >> 2, wn = warp & 3;

    float acc[4][4][4];
    #pragma unroll
    for (int i=0;i<4;i++)
        #pragma unroll
        for (int j=0;j<4;j++)
            #pragma unroll
            for (int q=0;q<4;q++) acc[i][j][q]=0.f;

    auto prefetch = [&](int ks, int buf){
        const int k0 = ks*32;
        #pragma unroll
        for (int s=0;s<2;s++){
            int c = t + s*256;
            int r = c >> 2, seg = c & 3;
            int gr = row0 + r;
            uint32_t dst = sptr(&Ash[buf][r*ALD2 + seg*8]);
            const void* src = A + (size_t)gr*K + k0 + seg*8;
            cpa16(dst, src, (gr < M) ? 16 : 0);
        }
        #pragma unroll
        for (int s=0;s<2;s++){
            int c = t + s*256;
            int r = c >> 4, seg = c & 15;
            uint32_t dst = sptr(&Bsh[buf][r*BLD + seg*8]);
            const void* src = Wh + (size_t)(k0 + r)*HID + col0 + seg*8;
            cpa16(dst, src, 16);
        }
    };

    auto compute = [&](int buf){
        #pragma unroll
        for (int h=0; h<2; h++){
            const int arow = wm*64 + (lane & 15);
            const int acol = h*16 + (lane >> 4)*8;
            uint32_t aA = sptr(&Ash[buf][0]) + (uint32_t)((arow*ALD2 + acol)*2);
            const int brow = h*16 + (lane & 15);
            const int bcol = wn*32 + (lane >> 4)*8;
            uint32_t bA = sptr(&Bsh[buf][0]) + (uint32_t)((brow*BLD + bcol)*2);

            uint32_t A_[4][4], B[4][2];
            #pragma unroll
            for (int mi=0; mi<4; mi++)
                ldsm4(A_[mi][0],A_[mi][1],A_[mi][2],A_[mi][3], aA + (uint32_t)(mi*16*ALD2*2));
            #pragma unroll
            for (int np=0; np<2; np++)
                ldsm4t(B[2*np][0],B[2*np][1],B[2*np+1][0],B[2*np+1][1],
                       bA + (uint32_t)(np*16*2));
            #pragma unroll
            for (int mi=0; mi<4; mi++)
                #pragma unroll
                for (int ni=0; ni<4; ni++)
                    mma16816h(acc[mi][ni], A_[mi], B[ni][0], B[ni][1]);
        }
    };

    const int KS = K/32;
    prefetch(0, 0); CP_COMMIT();
    int buf = 0;
    for (int ks=0; ks<KS; ks++){
        CP_WAIT0();
        __syncthreads();
        if (ks+1 < KS){ prefetch(ks+1, buf^1); CP_COMMIT(); }
        compute(buf);
        buf ^= 1;
    }

    const int gid = lane >> 2, tig = lane & 3;
    #pragma unroll
    for (int ni=0; ni<4; ni++){
        int c = col0 + wn*32 + ni*8 + tig*2;
        float2 bb = *(const float2*)(bias + c);
        #pragma unroll
        for (int mi=0; mi<4; mi++){
            int r = row0 + wm*64 + mi*16 + gid;
            if (r < M){
                __nv_bfloat162 o = __floats2bfloat162_rn(
                    fmaxf(acc[mi][ni][0] + bb.x, 0.f),
                    fmaxf(acc[mi][ni][1] + bb.y, 0.f));
                *(__nv_bfloat162*)(out + (size_t)r*HID + c) = o;
            }
            int r2 = r + 8;
            if (r2 < M){
                __nv_bfloat162 o = __floats2bfloat162_rn(
                    fmaxf(acc[mi][ni][2] + bb.x, 0.f),
                    fmaxf(acc[mi][ni][3] + bb.y, 0.f));
                *(__nv_bfloat162*)(out + (size_t)r2*HID + c) = o;
            }
        }
    }
}

// ---------------- multipool (dense bf16 input via mapidx) + output zeroing ----------------
__global__ void pool_kernel(const int* __restrict__ batches, float* out){
    const __nv_bfloat16* h = g_BA;   // dense layer-2 output
    __shared__ int idxs[SUBSZ];
    int t = threadIdx.x, b = blockIdx.x;
    if (b == 0 && t == 0) out[0] = 0.f;
    if (t < SUBSZ) idxs[t] = g_mapidx[batches[b*SUBSZ + t]];
    __syncthreads();
    float s = 0.f, mn = 3.4e38f, mx = -3.4e38f;
    #pragma unroll 8
    for (int m = 0; m < SUBSZ; m++){
        float v = __bfloat162float(h[(size_t)idxs[m]*HID + t]);
        s += v; mn = fminf(mn, v); mx = fmaxf(mx, v);
    }
    float* z = g_Z + (size_t)b*4*HID;
    z[t]         = s;
    z[HID + t]   = s * (1.0f/SUBSZ);
    z[2*HID + t] = mn;
    z[3*HID + t] = mx;
}

// ---------------- readout + BCE ----------------
__global__ __launch_bounds__(256)
void readout8(const float* __restrict__ Wr1, const float* __restrict__ br1,
              const float* __restrict__ Wr2, const float* __restrict__ br2,
              const float* __restrict__ labels, float* out){
    const int b0 = blockIdx.x*8;
    __shared__ float z[8*4*HID];
    int t = threadIdx.x;
    const float4* zg = (const float4*)(g_Z + (size_t)b0*4*HID);
    #pragma unroll
    for (int j = t; j < 8*4*HID/4; j += 256)
        ((float4*)z)[j] = zg[j];
    __syncthreads();

    float bb = br1[t];
    float acc[8];
    #pragma unroll
    for (int j=0;j<8;j++) acc[j] = bb;

    #pragma unroll 8
    for (int k=0;k<4*HID;k++){
        float w = Wr1[(size_t)k*HID + t];
        #pragma unroll
        for (int j=0;j<8;j++) acc[j] += z[j*4*HID + k]*w;
    }
    __syncthreads();
    float wr2 = Wr2[t];
    #pragma unroll
    for (int j=0;j<8;j++) z[j*HID + t] = fmaxf(acc[j], 0.f)*wr2;
    __syncthreads();

    int w = t >> 5, lane = t & 31;
    float s = 0.f;
    #pragma unroll
    for (int q=0;q<8;q++) s += z[w*HID + lane + q*32];
    #pragma unroll
    for (int off=16; off>0; off>>=1) s += __shfl_xor_sync(0xffffffffu, s, off);
    if (lane == 0){
        float p = s + br2[0];
        float l = labels[b0 + w];
        float term = fmaxf(p, 0.f) - p*l + log1pf(expf(-fabsf(p)));
        atomicAdd(out, term * (1.0f/NSUB));
    }
}

// ---------------- launch ----------------
static cudaStream_t g_s2 = nullptr;
static cudaEvent_t  g_evFork = nullptr, g_evJoin = nullptr, g_evList = nullptr;
static void* g_degPtr = nullptr;
static void* g_curPtr = nullptr;
static void* g_markPtr = nullptr;

extern "C" void kernel_launch(void* const* d_in, const int* in_sizes, int n_in,
                              void* d_out, int out_size){
    const float* x       = (const float*)d_in[0];
    const int*   esrc    = (const int*)  d_in[1];
    const int*   edst    = (const int*)  d_in[2];
    const float* ew      = (const float*)d_in[3];
    const int*   batches = (const int*)  d_in[4];
    const float* labels  = (const float*)d_in[6];
    const float* W0      = (const float*)d_in[7];
    const float* b0      = (const float*)d_in[8];
    const float* W1      = (const float*)d_in[9];
    const float* b1      = (const float*)d_in[10];
    const float* W2      = (const float*)d_in[11];
    const float* b2      = (const float*)d_in[12];
    const float* eps     = (const float*)d_in[13];
    const float* Wr1     = (const float*)d_in[14];
    const float* br1     = (const float*)d_in[15];
    const float* Wr2     = (const float*)d_in[16];
    const float* br2     = (const float*)d_in[17];
    float* out = (float*)d_out;

    if (!g_s2){
        cudaStreamCreateWithFlags(&g_s2, cudaStreamNonBlocking);
        cudaEventCreateWithFlags(&g_evFork, cudaEventDisableTiming);
        cudaEventCreateWithFlags(&g_evJoin, cudaEventDisableTiming);
        cudaEventCreateWithFlags(&g_evList, cudaEventDisableTiming);
        cudaGetSymbolAddress(&g_degPtr,  g_deg);
        cudaGetSymbolAddress(&g_curPtr,  g_cur);
        cudaGetSymbolAddress(&g_markPtr, g_mark);
    }

    cudaEventRecord(g_evFork, 0);
    cudaStreamWaitEvent(g_s2, g_evFork, 0);

    // main stream: input prep + weight conversion
    build_h0<<<4096, 256>>>(x);
    scatter_batch<<<(MTOT+255)/256, 256>>>(batches);
    build_w0h<<<(K0*HID+255)/256, 256>>>(W0);
    build_wh<<<(HID*HID+255)/256, 256>>>(W1, 1);
    build_wh<<<(HID*HID+255)/256, 256>>>(W2, 2);

    // side stream: CSR build (by dst)
    cudaMemsetAsync(g_degPtr, 0, NN*sizeof(int), g_s2);
    cudaMemsetAsync(g_curPtr, 0, NN*sizeof(int), g_s2);
    hist_dst<<<(NE+255)/256, 256, 0, g_s2>>>(edst);
    scan_block_s<<<NBLK, SCAN_B, 0, g_s2>>>(0);
    scan_bsums_s<<<1, 256, 0, g_s2>>>(0);
    scan_add_s<<<NBLK, SCAN_B, 0, g_s2>>>(0);
    csr_scatter<<<(NE+255)/256, 256, 0, g_s2>>>(esrc, edst, ew);
    cudaEventRecord(g_evJoin, g_s2);

    // side stream continues: marked-node compaction (needed only by layer 2)
    cudaMemsetAsync(g_markPtr, 0, NN*sizeof(int), g_s2);
    mark_nodes<<<(MTOT+255)/256, 256, 0, g_s2>>>(batches);
    scan_block_s<<<NBLK, SCAN_B, 0, g_s2>>>(1);
    scan_bsums_s<<<1, 256, 0, g_s2>>>(1);
    scan_add_s<<<NBLK, SCAN_B, 0, g_s2>>>(1);
    list_build<<<NBLK, SCAN_B, 0, g_s2>>>();
    cudaEventRecord(g_evList, g_s2);

    cudaStreamWaitEvent(0, g_evJoin, 0);

    dim3 gemmGrid(2, (NN+127)/128);
    const int gatherGrid = (NN+7)/8;

    // layer 0 (full)
    csr_gather<<<gatherGrid, 256>>>(0, eps, 0, K0, 33, 40);
    gemm_mma<K0><<<gemmGrid, 256>>>(0, b0, 1, 0);

    // layer 1 (full)
    csr_gather<<<gatherGrid, 256>>>(1, eps, 1, HID, 64, 64);
    gemm_mma<HID><<<gemmGrid, 256>>>(1, b1, 2, 0);

    // layer 2 (dense: only marked nodes)
    cudaStreamWaitEvent(0, g_evList, 0);
    csr_gather_d<<<gatherGrid, 256>>>(2, eps, 2);
    gemm_mma<HID><<<gemmGrid, 256>>>(2, b2, 1, 1);

    pool_kernel<<<NSUB, HID>>>(batches, out);
    readout8<<<NSUB/8, 256>>>(Wr1, br1, Wr2, br2, labels, out);
}